// round 16
// baseline (speedup 1.0000x reference)
#include <cuda_runtime.h>
#include <cuda_bf16.h>

#define BMAX 16384

typedef unsigned long long u64;

// Scratch (static device globals — no allocation).
// float2 view: g_U2[(p*10+o2)*B + b] = (U[b][p][2*o2], U[b][p][2*o2+1]),
// b_feat folded into U. Same for V. 10.5 MB each -> L2-resident.
__device__ float4 g_U4[8 * 10 * (BMAX / 2)];
__device__ float4 g_V4[8 * 10 * (BMAX / 2)];
// per-position relu(final) values, summed in groups of 7 by k3
__device__ float g_S[BMAX * 56];

// PHASE_LANES = [[1,3],[5,7],[0,2],[4,6],[0,1],[2,3],[4,5],[6,7]]
__device__ const int d_PLa[8] = {1, 5, 0, 4, 0, 2, 4, 6};
__device__ const int d_PLb[8] = {3, 7, 2, 6, 1, 3, 5, 7};

__device__ __forceinline__ float sigmoidf(float x) {
    return __fdividef(1.0f, 1.0f + __expf(-x));
}
__device__ __forceinline__ u64 pk2(float lo, float hi) {
    u64 r;
    asm("mov.b64 %0, {%1, %2};" : "=l"(r) : "f"(lo), "f"(hi));
    return r;
}
__device__ __forceinline__ void upk2(float& lo, float& hi, u64 v) {
    asm("mov.b64 {%0, %1}, %2;" : "=f"(lo), "=f"(hi) : "l"(v));
}
__device__ __forceinline__ u64 f2fma(u64 a, u64 b, u64 c) {
    u64 d;
    asm("fma.rn.f32x2 %0, %1, %2, %3;" : "=l"(d) : "l"(a), "l"(b), "l"(c));
    return d;
}
__device__ __forceinline__ u64 f2mul(u64 a, u64 b) {
    u64 d;
    asm("mul.rn.f32x2 %0, %1, %2;" : "=l"(d) : "l"(a), "l"(b));
    return d;
}
__device__ __forceinline__ u64 f2add(u64 a, u64 b) {
    u64 d;
    asm("add.rn.f32x2 %0, %1, %2;" : "=l"(d) : "l"(a), "l"(b));
    return d;
}
// relu applied to both packed halves
__device__ __forceinline__ u64 f2relu(u64 a) {
    float lo, hi;
    upk2(lo, hi, a);
    return pk2(fmaxf(lo, 0.0f), fmaxf(hi, 0.0f));
}

// ---------------------------------------------------------------------------
// Kernel 1: grid (B/256, 8); p = blockIdx.y, b fast across lanes.
// press-layer weights in ulonglong2 (half the LDS instrs of LDS.64 path).
// ---------------------------------------------------------------------------
__global__ void __launch_bounds__(256, 4)
frap_k1(const float* __restrict__ fi,
        const float* __restrict__ emb_phase,
        const float* __restrict__ w_veh,
        const float* __restrict__ b_veh,
        const float* __restrict__ w_line,
        const float* __restrict__ b_line,
        const float* __restrict__ w_feat,
        const float* __restrict__ b_feat,
        int B)
{
    __shared__ __align__(16) float s_fi[256 * 17];        // padded input tile
    __shared__ __align__(16) ulonglong2 s_wl4[64];        // [o][e]: dup-packed w_line pairs
    __shared__ __align__(16) ulonglong2 s_wproj[160];     // [o][c8]: (U-pair, V-pair)
    __shared__ u64   s_bline2[16];
    __shared__ float s_bfeat[20];
    __shared__ float s_sge[8];                            // sigmoid(emb_phase)
    __shared__ float s_wv[4], s_bv[4];

    int tx = threadIdx.x;
    int base = blockIdx.x * 256;

    // coalesced staging of the input tile (256 rows x 16 floats)
    {
        const float4* fi4 = (const float4*)(fi + (size_t)base * 16);
        for (int idx = tx; idx < 1024; idx += 256) {
            int r  = idx >> 2;
            int c4 = (idx & 3) * 4;
            if (base + r < B) {
                float4 v = fi4[idx];
                float* d = &s_fi[r * 17 + c4];
                d[0] = v.x; d[1] = v.y; d[2] = v.z; d[3] = v.w;
            }
        }
    }
    for (int idx = tx; idx < 64; idx += 256) {
        int o = idx >> 2, e = idx & 3;
        float w0 = w_line[o * 8 + 2 * e];
        float w1 = w_line[o * 8 + 2 * e + 1];
        ulonglong2 w4;
        w4.x = pk2(w0, w0);
        w4.y = pk2(w1, w1);
        s_wl4[idx] = w4;
    }
    for (int idx = tx; idx < 160; idx += 256) {
        int o = idx >> 3, c = idx & 7;                    // o<20, c = feature pair
        ulonglong2 w2;
        w2.x = pk2(w_feat[o * 32 + 2 * c],      w_feat[o * 32 + 2 * c + 1]);
        w2.y = pk2(w_feat[o * 32 + 16 + 2 * c], w_feat[o * 32 + 17 + 2 * c]);
        s_wproj[idx] = w2;
    }
    if (tx < 16) { float bl = b_line[tx]; s_bline2[tx] = pk2(bl, bl); }
    if (tx < 20) s_bfeat[tx] = b_feat[tx];
    if (tx < 8)  s_sge[tx]   = sigmoidf(emb_phase[tx]);
    if (tx < 4)  { s_wv[tx] = w_veh[tx]; s_bv[tx] = b_veh[tx]; }
    __syncthreads();

    int b = base + tx;
    if (b >= B) return;
    int p  = blockIdx.y;
    int la = d_PLa[p];
    int lb = d_PLb[p];

    const float* f = &s_fi[tx * 17];
    float bit_a = f[la],     bit_b = f[lb];
    float veh_a = f[8 + la], veh_b = f[8 + lb];
    int ia = (int)bit_a, ib = (int)bit_b;

    // packed line features: (laneA, laneB) per dim
    u64 lp[8];
#pragma unroll
    for (int d = 0; d < 4; d++) {
        lp[d]     = pk2(sigmoidf(veh_a * s_wv[d] + s_bv[d]),
                        sigmoidf(veh_b * s_wv[d] + s_bv[d]));
        lp[4 + d] = pk2(s_sge[ia * 4 + d], s_sge[ib * 4 + d]);
    }

    // press as natural pairs: pp[c] = (press[2c], press[2c+1])
    u64 pp[8];
    float pr_even = 0.0f;
#pragma unroll
    for (int o = 0; o < 16; o++) {
        u64 acc0 = s_bline2[o];
        u64 acc1 = pk2(0.0f, 0.0f);
#pragma unroll
        for (int e = 0; e < 2; e++) {
            ulonglong2 wlo = s_wl4[o * 4 + e];
            ulonglong2 whi = s_wl4[o * 4 + 2 + e];
            acc0 = f2fma(wlo.x, lp[2 * e],     acc0);
            acc0 = f2fma(wlo.y, lp[2 * e + 1], acc0);
            acc1 = f2fma(whi.x, lp[4 + 2 * e],     acc1);
            acc1 = f2fma(whi.y, lp[4 + 2 * e + 1], acc1);
        }
        u64 acc = f2add(acc0, acc1);
        float xa, xb;
        upk2(xa, xb, acc);
        float pr = fmaxf(xa, 0.0f) + fmaxf(xb, 0.0f);
        if (o & 1) pp[o >> 1] = pk2(pr_even, pr);
        else       pr_even = pr;
    }

    int Bh = B >> 1;
    float2* stU = (float2*)g_U4;
    float2* stV = (float2*)g_V4;
    size_t sidx = ((size_t)p * 10 * Bh) * 2 + b;   // float2 index [p*10+o2][b]

#pragma unroll 2
    for (int o2 = 0; o2 < 10; o2++) {
        float uo[2], vo[2];
#pragma unroll
        for (int s = 0; s < 2; s++) {
            int o = 2 * o2 + s;
            u64 accU = pk2(s_bfeat[o], 0.0f);      // bias in lo half
            u64 accV = pk2(0.0f, 0.0f);
#pragma unroll
            for (int c = 0; c < 8; c++) {
                ulonglong2 w2 = s_wproj[o * 8 + c];
                accU = f2fma(w2.x, pp[c], accU);
                accV = f2fma(w2.y, pp[c], accV);
            }
            float ul, uh, vl, vh;
            upk2(ul, uh, accU);
            upk2(vl, vh, accV);
            uo[s] = ul + uh;
            vo[s] = vl + vh;
        }
        stU[sidx + (size_t)o2 * B] = make_float2(uo[0], uo[1]);
        stV[sidx + (size_t)o2 * B] = make_float2(vo[0], vo[1]);
    }
}

// ---------------------------------------------------------------------------
// Kernel 2: grid (Bq/128, 56), Bq = B/4. pair = blockIdx.y (uniform pi/pj);
// thread handles 4 consecutive positions t = pair*B + 4*bq .. +3.
// Weight LDS amortized over 4 positions; 4 independent FMA chains;
// relu folded after the yc multiply (yc >= 0).
// ---------------------------------------------------------------------------
__global__ void __launch_bounds__(128, 4)
frap_k2(const float* __restrict__ emb_const,
        const float* __restrict__ w_const,
        const float* __restrict__ b_const,
        const float* __restrict__ w_comb,
        const float* __restrict__ b_comb,
        const float* __restrict__ w_final,
        const float* __restrict__ b_final,
        const int*   __restrict__ cmask,
        int B)
{
    __shared__ __align__(16) u64 s_ycp[56 * 10];  // [r][o2] = (yc[r][2o2], yc[r][2o2+1])
    __shared__ __align__(16) u64 s_w10[200];      // [o2][k] = (w[o2][2k], w[o2][2k+1])
    __shared__ float s_bc[20];
    __shared__ float s_wfin[20];
    __shared__ float s_bfin;

    int tx = threadIdx.x;
    for (int idx = tx; idx < 200; idx += 128) {
        int o2 = idx / 10, k = idx - o2 * 10;
        s_w10[idx] = pk2(w_comb[o2 * 20 + 2 * k], w_comb[o2 * 20 + 2 * k + 1]);
    }
    if (tx < 20) {
        s_bc[tx]   = b_comb[tx];
        s_wfin[tx] = w_final[tx];
    }
    if (tx == 0) s_bfin = b_final[0];
    for (int idx = tx; idx < 56 * 10; idx += 128) {
        int r  = idx / 10;
        int oc = idx - r * 10;
        const float* e  = emb_const + cmask[r] * 4;
        const float* w0 = w_const + (2 * oc) * 4;
        const float* w1 = w_const + (2 * oc + 1) * 4;
        float y0 = b_const[2 * oc]     + w0[0]*e[0] + w0[1]*e[1] + w0[2]*e[2] + w0[3]*e[3];
        float y1 = b_const[2 * oc + 1] + w1[0]*e[0] + w1[1]*e[1] + w1[2]*e[2] + w1[3]*e[3];
        s_ycp[idx] = pk2(fmaxf(y0, 0.0f), fmaxf(y1, 0.0f));
    }
    __syncthreads();

    int Bq = B >> 2;
    int Bh = B >> 1;
    int bq = blockIdx.x * 128 + tx;
    if (bq >= Bq) return;
    int pair = blockIdx.y;
    int pi = pair / 7;
    int r  = pair - pi * 7;
    int pj = r + (r >= pi ? 1 : 0);

    int t   = pair * B + 4 * bq;                  // multiple of 4
    int rem = t % 56;                             // multiple of 4, <= 52
    // yc rows rem..rem+3, each 10 u64 (80B, 16B-aligned)
    const ulonglong2* yr0 = (const ulonglong2*)(s_ycp + (rem    ) * 10);
    const ulonglong2* yr1 = (const ulonglong2*)(s_ycp + (rem + 1) * 10);
    const ulonglong2* yr2 = (const ulonglong2*)(s_ycp + (rem + 2) * 10);
    const ulonglong2* yr3 = (const ulonglong2*)(s_ycp + (rem + 3) * 10);

    int bh = 2 * bq;
    const float4* Ub = g_U4 + (size_t)pi * 10 * Bh + bh;
    const float4* Vb = g_V4 + (size_t)pj * 10 * Bh + bh;

    u64 H0[10], H1[10], H2[10], H3[10];           // feature-pair packed, 4 positions
#pragma unroll
    for (int k = 0; k < 5; k++) {
        ulonglong2 y0 = yr0[k], y1 = yr1[k], y2 = yr2[k], y3 = yr3[k];
#pragma unroll
        for (int s = 0; s < 2; s++) {             // o2 = 2k+s
            int o2 = 2 * k + s;
            float4 fu0 = Ub[(size_t)o2 * Bh];
            float4 fu1 = Ub[(size_t)o2 * Bh + 1];
            float4 fv0 = Vb[(size_t)o2 * Bh];
            float4 fv1 = Vb[(size_t)o2 * Bh + 1];
            u64 a0 = f2add(pk2(fu0.x, fu0.y), pk2(fv0.x, fv0.y));   // pos0
            u64 a1 = f2add(pk2(fu0.z, fu0.w), pk2(fv0.z, fv0.w));   // pos1
            u64 a2 = f2add(pk2(fu1.x, fu1.y), pk2(fv1.x, fv1.y));   // pos2
            u64 a3 = f2add(pk2(fu1.z, fu1.w), pk2(fv1.z, fv1.w));   // pos3
            u64 yc0 = s ? y0.y : y0.x;
            u64 yc1 = s ? y1.y : y1.x;
            u64 yc2 = s ? y2.y : y2.x;
            u64 yc3 = s ? y3.y : y3.x;
            H0[o2] = f2relu(f2mul(a0, yc0));      // relu after mul: yc >= 0
            H1[o2] = f2relu(f2mul(a1, yc1));
            H2[o2] = f2relu(f2mul(a2, yc2));
            H3[o2] = f2relu(f2mul(a3, yc3));
        }
    }

    float s0 = s_bfin, s1 = s_bfin, s2 = s_bfin, s3 = s_bfin;
#pragma unroll 4
    for (int o2 = 0; o2 < 20; o2++) {
        const ulonglong2* wr = (const ulonglong2*)(s_w10 + o2 * 10);
        float bc = s_bc[o2];
        u64 a0 = pk2(bc, 0.0f);
        u64 a1 = pk2(bc, 0.0f);
        u64 a2 = pk2(bc, 0.0f);
        u64 a3 = pk2(bc, 0.0f);
#pragma unroll
        for (int k = 0; k < 5; k++) {
            ulonglong2 w2 = wr[k];
            a0 = f2fma(w2.x, H0[2 * k], a0);
            a1 = f2fma(w2.x, H1[2 * k], a1);
            a2 = f2fma(w2.x, H2[2 * k], a2);
            a3 = f2fma(w2.x, H3[2 * k], a3);
            a0 = f2fma(w2.y, H0[2 * k + 1], a0);
            a1 = f2fma(w2.y, H1[2 * k + 1], a1);
            a2 = f2fma(w2.y, H2[2 * k + 1], a2);
            a3 = f2fma(w2.y, H3[2 * k + 1], a3);
        }
        float wf = s_wfin[o2];
        float l, h;
        upk2(l, h, a0); s0 += fmaxf(l + h, 0.0f) * wf;
        upk2(l, h, a1); s1 += fmaxf(l + h, 0.0f) * wf;
        upk2(l, h, a2); s2 += fmaxf(l + h, 0.0f) * wf;
        upk2(l, h, a3); s3 += fmaxf(l + h, 0.0f) * wf;
    }

    ((float4*)g_S)[(size_t)pair * Bq + bq] =
        make_float4(fmaxf(s0, 0.0f), fmaxf(s1, 0.0f),
                    fmaxf(s2, 0.0f), fmaxf(s3, 0.0f));
}

// ---------------------------------------------------------------------------
// Kernel 3: block-staged 7-sum. Block handles 256 outputs = 1792 g_S floats
// = 448 float4s, loaded coalesced into smem; per-thread stride-7 smem sum.
// ---------------------------------------------------------------------------
__global__ void __launch_bounds__(256, 8)
frap_k3(float* __restrict__ out, int n)
{
    __shared__ __align__(16) float s[1792];
    int tx = threadIdx.x;
    int obase = blockIdx.x * 256;
    size_t sbase = (size_t)obase * 7;

    const float4* g4 = (const float4*)(g_S + sbase);
    int lim = n * 7 - (int)sbase;                 // floats available
#pragma unroll
    for (int k = 0; k < 2; k++) {
        int idx = k * 256 + tx;                   // float4 index; 448 needed
        if (idx < 448 && idx * 4 < lim) {
            float4 v = g4[idx];
            float* d = &s[idx * 4];
            d[0] = v.x; d[1] = v.y; d[2] = v.z; d[3] = v.w;
        }
    }
    __syncthreads();

    int o = obase + tx;
    if (o >= n) return;
    const float* p = &s[tx * 7];
    out[o] = p[0] + p[1] + p[2] + p[3] + p[4] + p[5] + p[6];
}

// ---------------------------------------------------------------------------
extern "C" void kernel_launch(void* const* d_in, const int* in_sizes, int n_in,
                              void* d_out, int out_size)
{
    const float* fi        = (const float*)d_in[0];
    const float* emb_phase = (const float*)d_in[1];
    const float* w_veh     = (const float*)d_in[2];
    const float* b_veh     = (const float*)d_in[3];
    const float* w_line    = (const float*)d_in[4];
    const float* b_line    = (const float*)d_in[5];
    const float* emb_const = (const float*)d_in[6];
    const float* w_feat    = (const float*)d_in[7];
    const float* b_feat    = (const float*)d_in[8];
    const float* w_const   = (const float*)d_in[9];
    const float* b_const   = (const float*)d_in[10];
    const float* w_comb    = (const float*)d_in[11];
    const float* b_comb    = (const float*)d_in[12];
    const float* w_final   = (const float*)d_in[13];
    const float* b_final   = (const float*)d_in[14];
    const int*   cmask     = (const int*)d_in[15];

    int B = in_sizes[0] / 16;
    if (B > BMAX) B = BMAX;
    int Bq = B >> 2;

    dim3 grid1((B + 255) / 256, 8);
    dim3 grid2((Bq + 127) / 128, 56);
    int n = B * 8;
    int blocks3 = (n + 255) / 256;

    frap_k1<<<grid1, 256>>>(fi, emb_phase, w_veh, b_veh, w_line, b_line,
                            w_feat, b_feat, B);
    frap_k2<<<grid2, 128>>>(emb_const, w_const, b_const, w_comb, b_comb,
                            w_final, b_final, cmask, B);
    frap_k3<<<blocks3, 256>>>((float*)d_out, n);
}

// round 17
// speedup vs baseline: 1.1603x; 1.1603x over previous
#include <cuda_runtime.h>
#include <cuda_bf16.h>

#define BMAX 16384

typedef unsigned long long u64;

// Scratch (static device globals — no allocation).
// Pair-interleaved layout: g_U4[(p*10+o2)*Bh + bh] =
//   { U[2bh][p][2o2], U[2bh][p][2o2+1], U[2bh+1][p][2o2], U[2bh+1][p][2o2+1] }
// (b_feat folded into U). Same for V. 10.5 MB each -> L2-resident.
__device__ float4 g_U4[8 * 10 * (BMAX / 2)];
__device__ float4 g_V4[8 * 10 * (BMAX / 2)];

// PHASE_LANES = [[1,3],[5,7],[0,2],[4,6],[0,1],[2,3],[4,5],[6,7]]
__device__ const int d_PLa[8] = {1, 5, 0, 4, 0, 2, 4, 6};
__device__ const int d_PLb[8] = {3, 7, 2, 6, 1, 3, 5, 7};

__device__ __forceinline__ float sigmoidf(float x) {
    return __fdividef(1.0f, 1.0f + __expf(-x));
}
__device__ __forceinline__ u64 pk2(float lo, float hi) {
    u64 r;
    asm("mov.b64 %0, {%1, %2};" : "=l"(r) : "f"(lo), "f"(hi));
    return r;
}
__device__ __forceinline__ void upk2(float& lo, float& hi, u64 v) {
    asm("mov.b64 {%0, %1}, %2;" : "=f"(lo), "=f"(hi) : "l"(v));
}
__device__ __forceinline__ u64 f2fma(u64 a, u64 b, u64 c) {
    u64 d;
    asm("fma.rn.f32x2 %0, %1, %2, %3;" : "=l"(d) : "l"(a), "l"(b), "l"(c));
    return d;
}
__device__ __forceinline__ u64 f2mul(u64 a, u64 b) {
    u64 d;
    asm("mul.rn.f32x2 %0, %1, %2;" : "=l"(d) : "l"(a), "l"(b));
    return d;
}
__device__ __forceinline__ u64 f2add(u64 a, u64 b) {
    u64 d;
    asm("add.rn.f32x2 %0, %1, %2;" : "=l"(d) : "l"(a), "l"(b));
    return d;
}

// ---------------------------------------------------------------------------
// Kernel 1: grid (B/512, 8); p = blockIdx.y. Each thread handles TWO batch
// rows (2tx, 2tx+1 of a 512-row tile) so every weight LDS feeds 4 f2fma.
// p==0 blocks also zero d_out (k2 accumulates into it atomically).
// ---------------------------------------------------------------------------
__global__ void __launch_bounds__(256, 2)
frap_k1(const float* __restrict__ fi,
        const float* __restrict__ emb_phase,
        const float* __restrict__ w_veh,
        const float* __restrict__ b_veh,
        const float* __restrict__ w_line,
        const float* __restrict__ b_line,
        const float* __restrict__ w_feat,
        const float* __restrict__ b_feat,
        float* __restrict__ out,
        int B)
{
    __shared__ __align__(16) float s_fi[512 * 17];        // padded input tile (34.8KB)
    __shared__ __align__(16) ulonglong2 s_wl4[64];        // [o][e]: dup-packed w_line pairs
    __shared__ __align__(16) ulonglong2 s_wproj[160];     // [o][c8]: (U-pair, V-pair)
    __shared__ u64   s_bline2[16];
    __shared__ float s_bfeat[20];
    __shared__ float s_sge[8];                            // sigmoid(emb_phase)
    __shared__ float s_wv[4], s_bv[4];

    int tx = threadIdx.x;
    int base = blockIdx.x * 512;

    // coalesced staging of the input tile (512 rows x 16 floats = 2048 float4)
    {
        const float4* fi4 = (const float4*)(fi + (size_t)base * 16);
        for (int idx = tx; idx < 2048; idx += 256) {
            int r  = idx >> 2;
            int c4 = (idx & 3) * 4;
            if (base + r < B) {
                float4 v = fi4[idx];
                float* d = &s_fi[r * 17 + c4];
                d[0] = v.x; d[1] = v.y; d[2] = v.z; d[3] = v.w;
            }
        }
    }
    for (int idx = tx; idx < 64; idx += 256) {
        int o = idx >> 2, e = idx & 3;
        float w0 = w_line[o * 8 + 2 * e];
        float w1 = w_line[o * 8 + 2 * e + 1];
        ulonglong2 w4;
        w4.x = pk2(w0, w0);
        w4.y = pk2(w1, w1);
        s_wl4[idx] = w4;
    }
    for (int idx = tx; idx < 160; idx += 256) {
        int o = idx >> 3, c = idx & 7;                    // o<20, c = feature pair
        ulonglong2 w2;
        w2.x = pk2(w_feat[o * 32 + 2 * c],      w_feat[o * 32 + 2 * c + 1]);
        w2.y = pk2(w_feat[o * 32 + 16 + 2 * c], w_feat[o * 32 + 17 + 2 * c]);
        s_wproj[idx] = w2;
    }
    if (tx < 16) { float bl = b_line[tx]; s_bline2[tx] = pk2(bl, bl); }
    if (tx < 20) s_bfeat[tx] = b_feat[tx];
    if (tx < 8)  s_sge[tx]   = sigmoidf(emb_phase[tx]);
    if (tx < 4)  { s_wv[tx] = w_veh[tx]; s_bv[tx] = b_veh[tx]; }

    int p = blockIdx.y;
    // zero the output slab this block's rows own (k2 atomically accumulates)
    if (p == 0) {
        float4* o4 = (float4*)(out + (size_t)base * 8);
        float4 z = make_float4(0.0f, 0.0f, 0.0f, 0.0f);
        for (int idx = tx; idx < 1024; idx += 256) {      // 512 rows * 8 = 4096 floats
            if (base + (idx >> 1) < B) o4[idx] = z;
        }
    }
    __syncthreads();

    int b0 = base + 2 * tx;
    if (b0 >= B) return;
    int la = d_PLa[p];
    int lb = d_PLb[p];

    // packed line features for both rows
    u64 lpA[8], lpB[8];
#pragma unroll
    for (int row = 0; row < 2; row++) {
        const float* f = &s_fi[(2 * tx + row) * 17];
        u64* lp = row ? lpB : lpA;
        float bit_a = f[la],     bit_b = f[lb];
        float veh_a = f[8 + la], veh_b = f[8 + lb];
        int ia = (int)bit_a, ib = (int)bit_b;
#pragma unroll
        for (int d = 0; d < 4; d++) {
            lp[d]     = pk2(sigmoidf(veh_a * s_wv[d] + s_bv[d]),
                            sigmoidf(veh_b * s_wv[d] + s_bv[d]));
            lp[4 + d] = pk2(s_sge[ia * 4 + d], s_sge[ib * 4 + d]);
        }
    }

    // press pairs for both rows: weight LDS shared between rows
    u64 pp0[8], pp1[8];
    float prev0 = 0.0f, prev1 = 0.0f;
#pragma unroll
    for (int o = 0; o < 16; o++) {
        u64 a0A = s_bline2[o];
        u64 a1A = pk2(0.0f, 0.0f);
        u64 a0B = s_bline2[o];
        u64 a1B = pk2(0.0f, 0.0f);
#pragma unroll
        for (int e = 0; e < 2; e++) {
            ulonglong2 wlo = s_wl4[o * 4 + e];
            ulonglong2 whi = s_wl4[o * 4 + 2 + e];
            a0A = f2fma(wlo.x, lpA[2 * e],     a0A);
            a0A = f2fma(wlo.y, lpA[2 * e + 1], a0A);
            a1A = f2fma(whi.x, lpA[4 + 2 * e],     a1A);
            a1A = f2fma(whi.y, lpA[4 + 2 * e + 1], a1A);
            a0B = f2fma(wlo.x, lpB[2 * e],     a0B);
            a0B = f2fma(wlo.y, lpB[2 * e + 1], a0B);
            a1B = f2fma(whi.x, lpB[4 + 2 * e],     a1B);
            a1B = f2fma(whi.y, lpB[4 + 2 * e + 1], a1B);
        }
        float xa, xb, pr0, pr1;
        u64 accA = f2add(a0A, a1A);
        upk2(xa, xb, accA);
        pr0 = fmaxf(xa, 0.0f) + fmaxf(xb, 0.0f);
        u64 accB = f2add(a0B, a1B);
        upk2(xa, xb, accB);
        pr1 = fmaxf(xa, 0.0f) + fmaxf(xb, 0.0f);
        if (o & 1) {
            pp0[o >> 1] = pk2(prev0, pr0);
            pp1[o >> 1] = pk2(prev1, pr1);
        } else {
            prev0 = pr0;
            prev1 = pr1;
        }
    }

    int Bh = B >> 1;
    int bh = b0 >> 1;                                  // b0 even
    size_t sidx = (size_t)p * 10 * Bh + bh;

#pragma unroll 2
    for (int o2 = 0; o2 < 10; o2++) {
        float u0[2], v0[2], u1[2], v1[2];
#pragma unroll
        for (int s = 0; s < 2; s++) {
            int o = 2 * o2 + s;
            u64 aU0 = pk2(s_bfeat[o], 0.0f);           // (U incl bias, V)
            u64 aV0 = pk2(0.0f, 0.0f);
            u64 aU1 = pk2(s_bfeat[o], 0.0f);
            u64 aV1 = pk2(0.0f, 0.0f);
#pragma unroll
            for (int c = 0; c < 8; c++) {
                ulonglong2 w2 = s_wproj[o * 8 + c];
                aU0 = f2fma(w2.x, pp0[c], aU0);
                aV0 = f2fma(w2.y, pp0[c], aV0);
                aU1 = f2fma(w2.x, pp1[c], aU1);
                aV1 = f2fma(w2.y, pp1[c], aV1);
            }
            float ul, uh, vl, vh;
            upk2(ul, uh, aU0);
            upk2(vl, vh, aV0);
            u0[s] = ul + uh; v0[s] = vl + vh;
            upk2(ul, uh, aU1);
            upk2(vl, vh, aV1);
            u1[s] = ul + uh; v1[s] = vl + vh;
        }
        g_U4[sidx + (size_t)o2 * Bh] = make_float4(u0[0], u0[1], u1[0], u1[1]);
        g_V4[sidx + (size_t)o2 * Bh] = make_float4(v0[0], v0[1], v1[0], v1[1]);
    }
}

// ---------------------------------------------------------------------------
// Kernel 2: grid (Bh/256, 56). pair = blockIdx.y (warp-uniform pi/pj),
// thread handles positions t = pair*B + 2*bh, t+1 (coalesced gathers).
// Accumulates relu(final) directly into out[t/7] via atomicAdd (REDG).
// ---------------------------------------------------------------------------
__global__ void __launch_bounds__(256, 3)
frap_k2(const float* __restrict__ emb_const,
        const float* __restrict__ w_const,
        const float* __restrict__ b_const,
        const float* __restrict__ w_comb,
        const float* __restrict__ b_comb,
        const float* __restrict__ w_final,
        const float* __restrict__ b_final,
        const int*   __restrict__ cmask,
        float* __restrict__ out,
        int B)
{
    __shared__ __align__(16) u64 s_ycp[56 * 10];  // [r][o2] = (yc[r][2o2], yc[r][2o2+1])
    __shared__ __align__(16) u64 s_w10[200];      // [o2][k] = (w[o2][2k], w[o2][2k+1])
    __shared__ float s_bc[20];
    __shared__ float s_wfin[20];
    __shared__ float s_bfin;

    int tx = threadIdx.x;
    for (int idx = tx; idx < 200; idx += 256) {
        int o2 = idx / 10, k = idx - o2 * 10;
        s_w10[idx] = pk2(w_comb[o2 * 20 + 2 * k], w_comb[o2 * 20 + 2 * k + 1]);
    }
    if (tx < 20) {
        s_bc[tx]   = b_comb[tx];
        s_wfin[tx] = w_final[tx];
    }
    if (tx == 0) s_bfin = b_final[0];
    for (int idx = tx; idx < 56 * 10; idx += 256) {
        int r  = idx / 10;
        int oc = idx - r * 10;
        const float* e  = emb_const + cmask[r] * 4;
        const float* w0 = w_const + (2 * oc) * 4;
        const float* w1 = w_const + (2 * oc + 1) * 4;
        float y0 = b_const[2 * oc]     + w0[0]*e[0] + w0[1]*e[1] + w0[2]*e[2] + w0[3]*e[3];
        float y1 = b_const[2 * oc + 1] + w1[0]*e[0] + w1[1]*e[1] + w1[2]*e[2] + w1[3]*e[3];
        s_ycp[idx] = pk2(fmaxf(y0, 0.0f), fmaxf(y1, 0.0f));
    }
    __syncthreads();

    int Bh = B >> 1;
    int bh = blockIdx.x * 256 + tx;
    if (bh >= Bh) return;
    int pair = blockIdx.y;
    int pi = pair / 7;
    int r  = pair - pi * 7;
    int pj = r + (r >= pi ? 1 : 0);

    int t   = pair * B + 2 * bh;     // even
    int rem = t % 56;                // even
    const u64* ycp0 = s_ycp + rem * 10;        // pos0 row
    const u64* ycp1 = ycp0 + 10;               // pos1 row (rem+1 < 56)

    const float4* Ub = g_U4 + (size_t)pi * 10 * Bh + bh;
    const float4* Vb = g_V4 + (size_t)pj * 10 * Bh + bh;

    u64 Hp0[10], Hp1[10];                      // feature-pair packed per position
#pragma unroll
    for (int o2 = 0; o2 < 10; o2++) {
        float4 fu = Ub[(size_t)o2 * Bh];
        float4 fv = Vb[(size_t)o2 * Bh];
        Hp0[o2] = f2mul(pk2(fmaxf(fu.x + fv.x, 0.0f),
                            fmaxf(fu.y + fv.y, 0.0f)), ycp0[o2]);
        Hp1[o2] = f2mul(pk2(fmaxf(fu.z + fv.z, 0.0f),
                            fmaxf(fu.w + fv.w, 0.0f)), ycp1[o2]);
    }

    float s0 = s_bfin, s1 = s_bfin;
#pragma unroll 4
    for (int o2 = 0; o2 < 20; o2++) {
        const ulonglong2* wr = (const ulonglong2*)(s_w10 + o2 * 10);
        float bc = s_bc[o2];
        u64 a0 = pk2(bc, 0.0f);
        u64 a1 = pk2(bc, 0.0f);
#pragma unroll
        for (int k = 0; k < 5; k++) {
            ulonglong2 w2 = wr[k];
            a0 = f2fma(w2.x, Hp0[2 * k],     a0);
            a0 = f2fma(w2.y, Hp0[2 * k + 1], a0);
            a1 = f2fma(w2.x, Hp1[2 * k],     a1);
            a1 = f2fma(w2.y, Hp1[2 * k + 1], a1);
        }
        float l0, h0, l1, h1;
        upk2(l0, h0, a0);
        upk2(l1, h1, a1);
        float wf = s_wfin[o2];
        s0 += fmaxf(l0 + h0, 0.0f) * wf;
        s1 += fmaxf(l1 + h1, 0.0f) * wf;
    }

    float r0 = fmaxf(s0, 0.0f);
    float r1 = fmaxf(s1, 0.0f);
    int o0 = t / 7;
    int m  = t - o0 * 7;
    if (m == 6) {                      // positions straddle two outputs
        atomicAdd(out + o0,     r0);
        atomicAdd(out + o0 + 1, r1);
    } else {                           // same output: one atomic
        atomicAdd(out + o0, r0 + r1);
    }
}

// ---------------------------------------------------------------------------
extern "C" void kernel_launch(void* const* d_in, const int* in_sizes, int n_in,
                              void* d_out, int out_size)
{
    const float* fi        = (const float*)d_in[0];
    const float* emb_phase = (const float*)d_in[1];
    const float* w_veh     = (const float*)d_in[2];
    const float* b_veh     = (const float*)d_in[3];
    const float* w_line    = (const float*)d_in[4];
    const float* b_line    = (const float*)d_in[5];
    const float* emb_const = (const float*)d_in[6];
    const float* w_feat    = (const float*)d_in[7];
    const float* b_feat    = (const float*)d_in[8];
    const float* w_const   = (const float*)d_in[9];
    const float* b_const   = (const float*)d_in[10];
    const float* w_comb    = (const float*)d_in[11];
    const float* b_comb    = (const float*)d_in[12];
    const float* w_final   = (const float*)d_in[13];
    const float* b_final   = (const float*)d_in[14];
    const int*   cmask     = (const int*)d_in[15];

    int B = in_sizes[0] / 16;
    if (B > BMAX) B = BMAX;
    int Bh = B >> 1;

    dim3 grid1((B + 511) / 512, 8);
    dim3 grid2((Bh + 255) / 256, 56);

    frap_k1<<<grid1, 256>>>(fi, emb_phase, w_veh, b_veh, w_line, b_line,
                            w_feat, b_feat, (float*)d_out, B);
    frap_k2<<<grid2, 256>>>(emb_const, w_const, b_const, w_comb, b_comb,
                            w_final, b_final, cmask, (float*)d_out, B);
}